// round 2
// baseline (speedup 1.0000x reference)
#include <cuda_runtime.h>
#include <cstdint>
#include <math.h>

#define BATCH 4
#define NH 32
#define SEQQ 512
#define HD 128
#define NMEM 4096
#define MAXB 4
#define BQ 128
#define BK 64
#define NTHREADS 256
#define QK_LD 132     // floats per smem row for Q/K (pad 4 -> conflict-free QK^T frags)
#define V_LD 136      // floats per smem row for V   (pad 8 -> conflict-free PV frags)
#define LOG2E 1.4426950408889634f

// Scratch (static device globals: allocation-free per harness rules)
__device__ float g_Qr[BATCH * NH * SEQQ * HD];   // roped + scaled + tf32-rounded Q
__device__ float g_Kr[BATCH * NH * SEQQ * HD];   // roped + tf32-rounded K
__device__ float g_cos[SEQQ * (HD / 2)];
__device__ float g_sin[SEQQ * (HD / 2)];

__device__ __forceinline__ float tf32_rna(float x) {
    uint32_t u;
    asm("cvt.rna.tf32.f32 %0, %1;" : "=r"(u) : "f"(x));
    return __uint_as_float(u);
}

__device__ __forceinline__ void mma_tf32(float c[4],
                                         uint32_t a0, uint32_t a1, uint32_t a2, uint32_t a3,
                                         uint32_t b0, uint32_t b1) {
    asm volatile(
        "mma.sync.aligned.m16n8k8.row.col.f32.tf32.tf32.f32 "
        "{%0,%1,%2,%3}, {%4,%5,%6,%7}, {%8,%9}, {%0,%1,%2,%3};"
        : "+f"(c[0]), "+f"(c[1]), "+f"(c[2]), "+f"(c[3])
        : "r"(a0), "r"(a1), "r"(a2), "r"(a3), "r"(b0), "r"(b1));
}

__device__ __forceinline__ void cp16(void* dst, const void* src) {
    uint32_t d = (uint32_t)__cvta_generic_to_shared(dst);
    asm volatile("cp.async.cg.shared.global [%0], [%1], 16;" :: "r"(d), "l"(src));
}
__device__ __forceinline__ void cp16_zfill(void* dst, const void* src) {
    uint32_t d = (uint32_t)__cvta_generic_to_shared(dst);
    asm volatile("cp.async.cg.shared.global [%0], [%1], 16, 0;" :: "r"(d), "l"(src));
}

// ---------------------------------------------------------------------------
// Kernel 1: cos/sin table for positions [start, start+SEQQ), 64 freq pairs.
// fp64 angles: error vs exact ~0, so |mine - ref| is bounded by the reference's
// own fp32 rounding (~1.5e-4 in angle), well inside budget.
// ---------------------------------------------------------------------------
__global__ void rope_table_kernel(const int* __restrict__ start_ptr) {
    int idx = blockIdx.x * blockDim.x + threadIdx.x;
    if (idx >= SEQQ * (HD / 2)) return;
    int p  = idx & (HD / 2 - 1);
    int si = idx >> 6;
    double pos = (double)(*start_ptr + si);
    double inv = pow(10000.0, -((double)(2 * p)) / (double)HD);
    double ang = pos * inv;
    double s, c;
    sincos(ang, &s, &c);
    g_cos[idx] = (float)c;
    g_sin[idx] = (float)s;
}

// ---------------------------------------------------------------------------
// Kernel 2: apply RoPE to q (also * 1/sqrt(d)) and k; tf32-round; write scratch.
// Layout of q/k: [b, n, s, d]; position for row s is start + s.
// ---------------------------------------------------------------------------
__global__ void rope_apply_kernel(const float* __restrict__ q, const float* __restrict__ k) {
    int idx = blockIdx.x * blockDim.x + threadIdx.x;
    const int total = BATCH * NH * SEQQ * (HD / 4);
    if (idx >= 2 * total) return;
    bool isK = idx >= total;
    int t = isK ? idx - total : idx;
    int j4 = t & 31;                  // which float4 in the 128-wide row
    int si = (t >> 5) & (SEQQ - 1);   // s index within head

    float4 x = ((const float4*)(isK ? k : q))[t];
    int p0 = 2 * j4, p1 = 2 * j4 + 1;
    float c0 = g_cos[si * 64 + p0], s0 = g_sin[si * 64 + p0];
    float c1 = g_cos[si * 64 + p1], s1 = g_sin[si * 64 + p1];
    float4 y;
    y.x = x.x * c0 - x.y * s0;
    y.y = x.x * s0 + x.y * c0;
    y.z = x.z * c1 - x.w * s1;
    y.w = x.z * s1 + x.w * c1;
    if (isK) {
        y.x = tf32_rna(y.x); y.y = tf32_rna(y.y);
        y.z = tf32_rna(y.z); y.w = tf32_rna(y.w);
        ((float4*)g_Kr)[t] = y;
    } else {
        const float SC = 0.08838834764831845f;   // 1/sqrt(128)
        y.x = tf32_rna(y.x * SC); y.y = tf32_rna(y.y * SC);
        y.z = tf32_rna(y.z * SC); y.w = tf32_rna(y.w * SC);
        ((float4*)g_Qr)[t] = y;
    }
}

// ---------------------------------------------------------------------------
// Kernel 3: fused flash attention. Grid (SEQQ/BQ, BATCH*NH). 8 warps.
// Warp w owns query rows [w*16, w*16+16). mma m16n8k8 tf32.
// K source: t < start -> mem_kv[0][b,t,n,:] ; else g_Kr.   V analogous (v raw).
// ---------------------------------------------------------------------------
__global__ void __launch_bounds__(NTHREADS, 1)
attn_kernel(const float* __restrict__ mem_kv, const float* __restrict__ v_in,
            const int* __restrict__ start_ptr, float* __restrict__ out) {
    const int start = *start_ptr;
    const int T = start + SEQQ;
    const int ntiles = (T + BK - 1) / BK;
    const int qt = blockIdx.x;
    const int head = blockIdx.y;
    const int b = head >> 5;
    const int n = head & (NH - 1);
    const int tid = threadIdx.x;
    const int warp = tid >> 5;
    const int lane = tid & 31;
    const int g = lane >> 2;   // group id (row within 8)
    const int c = lane & 3;    // thread-in-group

    extern __shared__ float smem[];
    float* sQ = smem;                       // [BQ][QK_LD]
    float* sK = sQ + BQ * QK_LD;            // [2][BK][QK_LD]
    float* sV = sK + 2 * BK * QK_LD;        // [2][BK][V_LD]

    const float* vmem = mem_kv + (size_t)MAXB * NMEM * NH * HD;

    // ---- prologue: issue cp.async for KV tile 0 ----
    {
        for (int i = tid; i < BK * (HD / 4); i += NTHREADS) {
            int row = i >> 5, c4 = i & 31;
            int t = row;  // tile 0
            const float* src = (t < start)
                ? mem_kv + ((((size_t)b) * NMEM + t) * NH + n) * HD
                : g_Kr + (((size_t)(b * NH + n)) * SEQQ + (t - start)) * HD;
            cp16(sK + row * QK_LD + c4 * 4, src + c4 * 4);
        }
        for (int i = tid; i < BK * (HD / 4); i += NTHREADS) {
            int row = i >> 5, c4 = i & 31;
            int t = row;
            const float* src = (t < start)
                ? vmem + ((((size_t)b) * NMEM + t) * NH + n) * HD
                : v_in + (((size_t)(b * NH + n)) * SEQQ + (t - start)) * HD;
            cp16(sV + row * V_LD + c4 * 4, src + c4 * 4);
        }
        asm volatile("cp.async.commit_group;");
    }

    // ---- load Q tile (already roped/scaled/tf32) ----
    {
        size_t gq = ((size_t)(b * NH + n)) * SEQQ + (size_t)qt * BQ;
        for (int i = tid; i < BQ * (HD / 4); i += NTHREADS) {
            int row = i >> 5, c4 = i & 31;
            float4 x = ((const float4*)(g_Qr + (gq + row) * HD))[c4];
            *(float4*)(sQ + row * QK_LD + c4 * 4) = x;
        }
    }

    float o[16][4];
#pragma unroll
    for (int i = 0; i < 16; i++)
#pragma unroll
        for (int j = 0; j < 4; j++) o[i][j] = 0.f;
    float m0 = -1e30f, m1 = -1e30f, l0 = 0.f, l1 = 0.f;

    for (int kt = 0; kt < ntiles; kt++) {
        int buf = kt & 1;

        // prefetch next tile into other buffer
        if (kt + 1 < ntiles) {
            int t0 = (kt + 1) * BK;
            float* dK = sK + (buf ^ 1) * BK * QK_LD;
            float* dV = sV + (buf ^ 1) * BK * V_LD;
            for (int i = tid; i < BK * (HD / 4); i += NTHREADS) {
                int row = i >> 5, c4 = i & 31;
                int t = t0 + row;
                if (t >= T) { cp16_zfill(dK + row * QK_LD + c4 * 4, mem_kv); continue; }
                const float* src = (t < start)
                    ? mem_kv + ((((size_t)b) * NMEM + t) * NH + n) * HD
                    : g_Kr + (((size_t)(b * NH + n)) * SEQQ + (t - start)) * HD;
                cp16(dK + row * QK_LD + c4 * 4, src + c4 * 4);
            }
            for (int i = tid; i < BK * (HD / 4); i += NTHREADS) {
                int row = i >> 5, c4 = i & 31;
                int t = t0 + row;
                if (t >= T) { cp16_zfill(dV + row * V_LD + c4 * 4, mem_kv); continue; }
                const float* src = (t < start)
                    ? vmem + ((((size_t)b) * NMEM + t) * NH + n) * HD
                    : v_in + (((size_t)(b * NH + n)) * SEQQ + (t - start)) * HD;
                cp16(dV + row * V_LD + c4 * 4, src + c4 * 4);
            }
            asm volatile("cp.async.commit_group;");
            asm volatile("cp.async.wait_group 1;");
        } else {
            asm volatile("cp.async.wait_group 0;");
        }
        __syncthreads();

        const float* Kb = sK + buf * BK * QK_LD;
        const float* Vb = sV + buf * BK * V_LD;
        const float* Qw = sQ + (warp * 16) * QK_LD;

        // ---- S = Q K^T (16 x 64 per warp) ----
        float s[8][4];
#pragma unroll
        for (int i = 0; i < 8; i++)
#pragma unroll
            for (int j = 0; j < 4; j++) s[i][j] = 0.f;

#pragma unroll
        for (int dk = 0; dk < 16; dk++) {
            const int dc = dk * 8;
            uint32_t a0 = __float_as_uint(Qw[g * QK_LD + dc + c]);
            uint32_t a1 = __float_as_uint(Qw[(g + 8) * QK_LD + dc + c]);
            uint32_t a2 = __float_as_uint(Qw[g * QK_LD + dc + c + 4]);
            uint32_t a3 = __float_as_uint(Qw[(g + 8) * QK_LD + dc + c + 4]);
#pragma unroll
            for (int nt = 0; nt < 8; nt++) {
                uint32_t b0 = __float_as_uint(Kb[(nt * 8 + g) * QK_LD + dc + c]);
                uint32_t b1 = __float_as_uint(Kb[(nt * 8 + g) * QK_LD + dc + c + 4]);
                mma_tf32(s[nt], a0, a1, a2, a3, b0, b1);
            }
        }

        // ---- mask tail keys (only ever taken if T % BK != 0) ----
        int t0k = kt * BK;
        if (t0k + BK > T) {
#pragma unroll
            for (int nt = 0; nt < 8; nt++) {
                int tc = t0k + nt * 8 + 2 * c;
                if (tc     >= T) { s[nt][0] = -1e30f; s[nt][2] = -1e30f; }
                if (tc + 1 >= T) { s[nt][1] = -1e30f; s[nt][3] = -1e30f; }
            }
        }

        // ---- online softmax (rows g and g+8; quad lanes share a row) ----
        float mloc0 = -1e30f, mloc1 = -1e30f;
#pragma unroll
        for (int nt = 0; nt < 8; nt++) {
            mloc0 = fmaxf(mloc0, fmaxf(s[nt][0], s[nt][1]));
            mloc1 = fmaxf(mloc1, fmaxf(s[nt][2], s[nt][3]));
        }
        mloc0 = fmaxf(mloc0, __shfl_xor_sync(0xffffffffu, mloc0, 1));
        mloc0 = fmaxf(mloc0, __shfl_xor_sync(0xffffffffu, mloc0, 2));
        mloc1 = fmaxf(mloc1, __shfl_xor_sync(0xffffffffu, mloc1, 1));
        mloc1 = fmaxf(mloc1, __shfl_xor_sync(0xffffffffu, mloc1, 2));
        float mn0 = fmaxf(m0, mloc0), mn1 = fmaxf(m1, mloc1);
        float al0 = exp2f((m0 - mn0) * LOG2E);
        float al1 = exp2f((m1 - mn1) * LOG2E);
        m0 = mn0; m1 = mn1;

        float ll0 = 0.f, ll1 = 0.f;
#pragma unroll
        for (int nt = 0; nt < 8; nt++) {
            float p00 = exp2f((s[nt][0] - m0) * LOG2E);
            float p01 = exp2f((s[nt][1] - m0) * LOG2E);
            float p10 = exp2f((s[nt][2] - m1) * LOG2E);
            float p11 = exp2f((s[nt][3] - m1) * LOG2E);
            ll0 += p00 + p01;
            ll1 += p10 + p11;
            s[nt][0] = tf32_rna(p00); s[nt][1] = tf32_rna(p01);
            s[nt][2] = tf32_rna(p10); s[nt][3] = tf32_rna(p11);
        }
        l0 = l0 * al0 + ll0;
        l1 = l1 * al1 + ll1;
#pragma unroll
        for (int i = 0; i < 16; i++) {
            o[i][0] *= al0; o[i][1] *= al0;
            o[i][2] *= al1; o[i][3] *= al1;
        }

        // ---- O += P V  (P: C-layout -> A-layout via quad shuffles) ----
        const int baseLane = lane & ~3;
#pragma unroll
        for (int kk = 0; kk < 8; kk++) {
            uint32_t p0 = __float_as_uint(s[kk][0]);
            uint32_t p1 = __float_as_uint(s[kk][1]);
            uint32_t p2 = __float_as_uint(s[kk][2]);
            uint32_t p3 = __float_as_uint(s[kk][3]);
            int src0 = baseLane + (c >> 1);
            int src2 = src0 + 2;
            uint32_t q00 = __shfl_sync(0xffffffffu, p0, src0);
            uint32_t q01 = __shfl_sync(0xffffffffu, p1, src0);
            uint32_t q20 = __shfl_sync(0xffffffffu, p0, src2);
            uint32_t q21 = __shfl_sync(0xffffffffu, p1, src2);
            uint32_t q10 = __shfl_sync(0xffffffffu, p2, src0);
            uint32_t q11 = __shfl_sync(0xffffffffu, p3, src0);
            uint32_t q30 = __shfl_sync(0xffffffffu, p2, src2);
            uint32_t q31 = __shfl_sync(0xffffffffu, p3, src2);
            bool odd = (c & 1);
            uint32_t a0 = odd ? q01 : q00;
            uint32_t a1 = odd ? q11 : q10;
            uint32_t a2 = odd ? q21 : q20;
            uint32_t a3 = odd ? q31 : q30;
#pragma unroll
            for (int dt = 0; dt < 16; dt++) {
                uint32_t b0 = __float_as_uint(Vb[(kk * 8 + c) * V_LD + dt * 8 + g]);
                uint32_t b1 = __float_as_uint(Vb[(kk * 8 + c + 4) * V_LD + dt * 8 + g]);
                mma_tf32(o[dt], a0, a1, a2, a3, b0, b1);
            }
        }
        __syncthreads();
    }

    // ---- epilogue: normalize and store ----
    l0 += __shfl_xor_sync(0xffffffffu, l0, 1);
    l0 += __shfl_xor_sync(0xffffffffu, l0, 2);
    l1 += __shfl_xor_sync(0xffffffffu, l1, 1);
    l1 += __shfl_xor_sync(0xffffffffu, l1, 2);
    float inv0 = 1.f / l0, inv1 = 1.f / l1;

    size_t obase = (((size_t)(b * NH + n)) * SEQQ + (size_t)qt * BQ + warp * 16) * HD;
#pragma unroll
    for (int dt = 0; dt < 16; dt++) {
        float2 w0 = make_float2(o[dt][0] * inv0, o[dt][1] * inv0);
        float2 w1 = make_float2(o[dt][2] * inv1, o[dt][3] * inv1);
        *(float2*)(out + obase + (size_t)g * HD + dt * 8 + 2 * c) = w0;
        *(float2*)(out + obase + (size_t)(g + 8) * HD + dt * 8 + 2 * c) = w1;
    }
}

// ---------------------------------------------------------------------------
extern "C" void kernel_launch(void* const* d_in, const int* in_sizes, int n_in,
                              void* d_out, int out_size) {
    const float* q      = (const float*)d_in[0];
    const float* k      = (const float*)d_in[1];
    const float* v      = (const float*)d_in[2];
    const float* mem_kv = (const float*)d_in[3];
    const int*   start  = (const int*)d_in[4];
    float* out = (float*)d_out;

    rope_table_kernel<<<(SEQQ * (HD / 2) + 255) / 256, 256>>>(start);

    int total4 = 2 * BATCH * NH * SEQQ * (HD / 4);
    rope_apply_kernel<<<(total4 + 255) / 256, 256>>>(q, k);

    int smem = (BQ * QK_LD + 2 * BK * QK_LD + 2 * BK * V_LD) * (int)sizeof(float); // 204800 B
    cudaFuncSetAttribute(attn_kernel, cudaFuncAttributeMaxDynamicSharedMemorySize, smem);
    dim3 grid(SEQQ / BQ, BATCH * NH);
    attn_kernel<<<grid, NTHREADS, smem>>>(mem_kv, v, start, out);
}